// round 4
// baseline (speedup 1.0000x reference)
#include <cuda_runtime.h>
#include <cuda_bf16.h>

// Align2D: bilinear warp (grid_sample, border padding) of x[8,64,512,512]
// by flow[8,2,512,512]. Output = concat(x_warp flattened, flow flattened).
//
// R3: two horizontally-adjacent pixels per thread.
//  - float2 flow loads (8B-aligned since pair starts at even x)
//  - float2 output stores (halves store instruction count)
//  - 8 independent gathers per channel iteration -> higher MLP
//  - tap indices/weights computed once per pixel pair, amortized over C=64

#define BB 8
#define CC 64
#define HH 512
#define WW 512
#define HWP (HH * WW)

__global__ __launch_bounds__(256) void align2d_warp_kernel(
    const float* __restrict__ x,
    const float* __restrict__ flow,
    float* __restrict__ out)
{
    int pair = blockIdx.x * blockDim.x + threadIdx.x;   // 0 .. B*H*W/2-1
    if (pair >= BB * HWP / 2) return;

    int pix = pair << 1;               // even pixel index
    int b = pix >> 18;                 // / HWP
    int p = pix & (HWP - 1);           // y*W + x  (x even)
    int yi = p >> 9;
    int xi = p & (WW - 1);

    // flow loads: float2 covers both pixels of the pair (8B aligned)
    const float* fbase = flow + (size_t)b * 2 * HWP + p;
    float2 fx2 = *(const float2*)fbase;          // flow_x for pix, pix+1
    float2 fy2 = *(const float2*)(fbase + HWP);  // flow_y for pix, pix+1

    // ---- pixel A (xi) ----
    float pxA = fminf(fmaxf((float)xi + fx2.x, 0.0f), (float)(WW - 1));
    float pyA = fminf(fmaxf((float)yi + fy2.x, 0.0f), (float)(HH - 1));
    float x0fA = floorf(pxA), y0fA = floorf(pyA);
    float wxA = pxA - x0fA,  wyA = pyA - y0fA;
    int x0A = (int)x0fA, y0A = (int)y0fA;
    int x1A = min(x0A + 1, WW - 1);
    int y1A = min(y0A + 1, HH - 1);
    int a00 = y0A * WW + x0A, a01 = y0A * WW + x1A;
    int a10 = y1A * WW + x0A, a11 = y1A * WW + x1A;
    float wA00 = (1.0f - wxA) * (1.0f - wyA);
    float wA01 = wxA * (1.0f - wyA);
    float wA10 = (1.0f - wxA) * wyA;
    float wA11 = wxA * wyA;

    // ---- pixel B (xi+1) ----
    float pxB = fminf(fmaxf((float)(xi + 1) + fx2.y, 0.0f), (float)(WW - 1));
    float pyB = fminf(fmaxf((float)yi + fy2.y, 0.0f), (float)(HH - 1));
    float x0fB = floorf(pxB), y0fB = floorf(pyB);
    float wxB = pxB - x0fB,  wyB = pyB - y0fB;
    int x0B = (int)x0fB, y0B = (int)y0fB;
    int x1B = min(x0B + 1, WW - 1);
    int y1B = min(y0B + 1, HH - 1);
    int b00 = y0B * WW + x0B, b01 = y0B * WW + x1B;
    int b10 = y1B * WW + x0B, b11 = y1B * WW + x1B;
    float wB00 = (1.0f - wxB) * (1.0f - wyB);
    float wB01 = wxB * (1.0f - wyB);
    float wB10 = (1.0f - wxB) * wyB;
    float wB11 = wxB * wyB;

    const float* xb = x   + (size_t)b * CC * HWP;
    float*       ob = out + (size_t)b * CC * HWP + p;

    #pragma unroll 4
    for (int c = 0; c < CC; c++) {
        const float* xc = xb + (size_t)c * HWP;
        float vA00 = __ldg(xc + a00);
        float vA01 = __ldg(xc + a01);
        float vA10 = __ldg(xc + a10);
        float vA11 = __ldg(xc + a11);
        float vB00 = __ldg(xc + b00);
        float vB01 = __ldg(xc + b01);
        float vB10 = __ldg(xc + b10);
        float vB11 = __ldg(xc + b11);
        float2 v;
        v.x = fmaf(vA00, wA00, fmaf(vA01, wA01, fmaf(vA10, wA10, vA11 * wA11)));
        v.y = fmaf(vB00, wB00, fmaf(vB01, wB01, fmaf(vB10, wB10, vB11 * wB11)));
        *(float2*)(ob + (size_t)c * HWP) = v;
    }
}

extern "C" void kernel_launch(void* const* d_in, const int* in_sizes, int n_in,
                              void* d_out, int out_size)
{
    const float* x    = (const float*)d_in[0];
    const float* flow = (const float*)d_in[1];
    float*       out  = (float*)d_out;

    int npairs = BB * HWP / 2;              // 1,048,576
    int threads = 256;
    int blocks = (npairs + threads - 1) / threads;
    align2d_warp_kernel<<<blocks, threads>>>(x, flow, out);

    // flow passthrough: second output component appended after warp output
    size_t warp_elems = (size_t)BB * CC * HWP;
    size_t flow_bytes = (size_t)BB * 2 * HWP * sizeof(float);
    cudaMemcpyAsync(out + warp_elems, flow, flow_bytes,
                    cudaMemcpyDeviceToDevice);
}